// round 15
// baseline (speedup 1.0000x reference)
#include <cuda_runtime.h>
#include <cuda_bf16.h>
#include <cstdint>

// ---------------------------------------------------------------------------
// Transformer block: B=4, S=2048, DIM=1024, 16 heads, dph=64
// All matmuls on tensor cores via mma.sync split-bf16 (hi/lo).
// GEMM: CTA 128x128, 4 warps (64x64 warp tile), 4-stage cp.async ring.
// Attention: flash w/ 2-stage cp.async K/V double-buffer.
// ---------------------------------------------------------------------------

#define B_ 4
#define S_ 2048
#define DIM_ 1024
#define NH_ 16
#define DPH_ 64
#define M_TOK (B_ * S_)        // 8192
#define HID_ (4 * DIM_)        // 4096

typedef __nv_bfloat16 bf16;

// fp32 scratch
__device__ float g_attn[M_TOK * DIM_];
__device__ float g_h[M_TOK * DIM_];
__device__ float g_ffn[M_TOK * DIM_];
// bf16 hi/lo operand scratch (weights in natural [K][N] layout)
__device__ bf16 g_xhi[M_TOK * DIM_],  g_xlo[M_TOK * DIM_];
__device__ bf16 g_wqhi[DIM_ * DIM_],  g_wqlo[DIM_ * DIM_];
__device__ bf16 g_wkhi[DIM_ * DIM_],  g_wklo[DIM_ * DIM_];
__device__ bf16 g_wvhi[DIM_ * DIM_],  g_wvlo[DIM_ * DIM_];
__device__ bf16 g_w1hi[DIM_ * HID_],  g_w1lo[DIM_ * HID_];
__device__ bf16 g_w2hi[HID_ * DIM_],  g_w2lo[HID_ * DIM_];
__device__ bf16 g_qhi[M_TOK * DIM_],  g_qlo[M_TOK * DIM_];
__device__ bf16 g_khi[M_TOK * DIM_],  g_klo[M_TOK * DIM_];
__device__ bf16 g_vhi[M_TOK * DIM_],  g_vlo[M_TOK * DIM_];
__device__ bf16 g_hhi[M_TOK * DIM_],  g_hlo[M_TOK * DIM_];
__device__ bf16 g_midhi[M_TOK * HID_], g_midlo[M_TOK * HID_];

// ---------------------------------------------------------------------------
// helpers
// ---------------------------------------------------------------------------
__device__ __forceinline__ void ldsm_x4(uint32_t (&r)[4], uint32_t addr) {
    asm volatile("ldmatrix.sync.aligned.m8n8.x4.shared.b16 {%0,%1,%2,%3}, [%4];"
                 : "=r"(r[0]), "=r"(r[1]), "=r"(r[2]), "=r"(r[3]) : "r"(addr));
}
__device__ __forceinline__ void ldsm_x4t(uint32_t (&r)[4], uint32_t addr) {
    asm volatile("ldmatrix.sync.aligned.m8n8.x4.trans.shared.b16 {%0,%1,%2,%3}, [%4];"
                 : "=r"(r[0]), "=r"(r[1]), "=r"(r[2]), "=r"(r[3]) : "r"(addr));
}
__device__ __forceinline__ void mma16816(float (&d)[4], const uint32_t (&a)[4],
                                         uint32_t b0, uint32_t b1) {
    asm volatile(
        "mma.sync.aligned.m16n8k16.row.col.f32.bf16.bf16.f32 "
        "{%0,%1,%2,%3}, {%4,%5,%6,%7}, {%8,%9}, {%0,%1,%2,%3};"
        : "+f"(d[0]), "+f"(d[1]), "+f"(d[2]), "+f"(d[3])
        : "r"(a[0]), "r"(a[1]), "r"(a[2]), "r"(a[3]), "r"(b0), "r"(b1));
}
__device__ __forceinline__ void cvt2(float x, float y, uint32_t& hi, uint32_t& lo) {
    bf16 hx = __float2bfloat16_rn(x);
    bf16 hy = __float2bfloat16_rn(y);
    bf16 lx = __float2bfloat16_rn(x - __bfloat162float(hx));
    bf16 ly = __float2bfloat16_rn(y - __bfloat162float(hy));
    hi = (uint32_t)__bfloat16_as_ushort(hx) | ((uint32_t)__bfloat16_as_ushort(hy) << 16);
    lo = (uint32_t)__bfloat16_as_ushort(lx) | ((uint32_t)__bfloat16_as_ushort(ly) << 16);
}
__device__ __forceinline__ void cp16(uint32_t dst, const void* src) {
    asm volatile("cp.async.cg.shared.global [%0], [%1], 16;" :: "r"(dst), "l"(src));
}

// ---------------------------------------------------------------------------
// elementwise split: fp32 -> bf16 hi/lo
// ---------------------------------------------------------------------------
__global__ void __launch_bounds__(256)
split_kernel(const float* __restrict__ in, bf16* __restrict__ hi,
             bf16* __restrict__ lo, int n4) {
    int i = blockIdx.x * blockDim.x + threadIdx.x;
    if (i < n4) {
        float4 v = ((const float4*)in)[i];
        uint32_t h0, l0, h1, l1;
        cvt2(v.x, v.y, h0, l0); cvt2(v.z, v.w, h1, l1);
        ((uint2*)hi)[i] = make_uint2(h0, h1);
        ((uint2*)lo)[i] = make_uint2(l0, l1);
    }
}

// ---------------------------------------------------------------------------
// Tensor-core GEMM: CTA 128x128, 128 threads (4 warps, 2m x 2n, warp 64x64),
// k-step 16, 4-stage cp.async ring. Split-bf16 (3 mma per logical mma).
// ---------------------------------------------------------------------------
#define AS 24          // A smem row stride (bf16) = 48B
#define BS 136         // B smem row stride (bf16) = 272B
#define A_BYTES (128 * AS * 2)          // 6144
#define B_BYTES (16 * BS * 2)           // 4352
#define SSTRIDE (2 * A_BYTES + 2 * B_BYTES)   // 20992 per stage
#define STAGES 4
#define GEMM_SMEM (STAGES * SSTRIDE)    // 83968

template <bool RELU, bool WF32, bool WHILO>
__global__ void __launch_bounds__(128, 2)
gemm_mma_kernel(const bf16* __restrict__ Ahi, const bf16* __restrict__ Alo,
                const bf16* __restrict__ Bhi, const bf16* __restrict__ Blo,
                const float* __restrict__ bias, float* __restrict__ C,
                bf16* __restrict__ Chi, bf16* __restrict__ Clo,
                int M, int N, int K) {
    extern __shared__ char smem[];
    const uint32_t sbase = (uint32_t)__cvta_generic_to_shared(smem);

    const int tid  = threadIdx.x;
    const int lane = tid & 31;
    const int wid  = tid >> 5;
    const int wm   = wid & 1;       // 64-row half
    const int wn   = wid >> 1;      // 64-col half
    const int m0 = blockIdx.y << 7;
    const int n0 = blockIdx.x << 7;

    // loaders (128 threads)
    // A: thread t -> row t, two 16B chunks (cols 0-7, 8-15), hi & lo
    const bf16* Aph = Ahi + (long)(m0 + tid) * K;
    const bf16* Apl = Alo + (long)(m0 + tid) * K;
    const uint32_t aHd = sbase + (tid * AS) * 2;
    // B: thread t -> k-row t>>3, col (t&7)*16; TWO 16B chunks per hi/lo buffer
    const int bk = tid >> 3;
    const int bc = (tid & 7) << 4;
    const bf16* Bph = Bhi + (long)bk * N + n0 + bc;
    const bf16* Bpl = Blo + (long)bk * N + n0 + bc;
    const uint32_t bHd = sbase + 2 * A_BYTES + (bk * BS + bc) * 2;

    // ldmatrix offsets (within a stage)
    const int arow = lane & 15;
    const int acolg = (lane >> 4) << 3;
    uint32_t aOffHi[4], aOffLo[4];
#pragma unroll
    for (int mi = 0; mi < 4; mi++) {
        int off = ((wm * 64 + mi * 16 + arow) * AS + acolg) * 2;
        aOffHi[mi] = sbase + off;
        aOffLo[mi] = sbase + A_BYTES + off;
    }
    const int bRow = lane & 15;
    const int bNdSel = (lane >> 4) & 1;
    uint32_t bOffHi[4], bOffLo[4];
#pragma unroll
    for (int np = 0; np < 4; np++) {
        int off = (bRow * BS + wn * 64 + (2 * np + bNdSel) * 8) * 2;
        bOffHi[np] = sbase + 2 * A_BYTES + off;
        bOffLo[np] = sbase + 2 * A_BYTES + B_BYTES + off;
    }

    float acc[4][8][4];
#pragma unroll
    for (int mi = 0; mi < 4; mi++)
#pragma unroll
        for (int ni = 0; ni < 8; ni++)
#pragma unroll
            for (int r = 0; r < 4; r++) acc[mi][ni][r] = 0.f;

    const int nk = K >> 4;

    auto issue_stage = [&](int s, int k0) {
        const uint32_t so = s * SSTRIDE;
        cp16(aHd + so,      Aph + k0);
        cp16(aHd + so + 16, Aph + k0 + 8);
        cp16(aHd + so + A_BYTES,      Apl + k0);
        cp16(aHd + so + A_BYTES + 16, Apl + k0 + 8);
        cp16(bHd + so,      Bph + (long)k0 * N);
        cp16(bHd + so + 16, Bph + (long)k0 * N + 8);
        cp16(bHd + so + B_BYTES,      Bpl + (long)k0 * N);
        cp16(bHd + so + B_BYTES + 16, Bpl + (long)k0 * N + 8);
    };

    // prologue: stages 0..2
    issue_stage(0, 0);
    asm volatile("cp.async.commit_group;");
    if (nk > 1) issue_stage(1, 16);
    asm volatile("cp.async.commit_group;");
    if (nk > 2) issue_stage(2, 32);
    asm volatile("cp.async.commit_group;");

    int sc = 0;   // stage being computed
    for (int kt = 0; kt < nk; kt++) {
        asm volatile("cp.async.wait_group %0;" :: "n"(STAGES - 2));
        __syncthreads();

        // issue stage kt+3
        if (kt + 3 < nk) {
            int sw = sc + 3; if (sw >= STAGES) sw -= STAGES;
            issue_stage(sw, (kt + 3) << 4);
        }
        asm volatile("cp.async.commit_group;");

        // compute stage sc
        const uint32_t so = sc * SSTRIDE;
        uint32_t ahi[4][4], alo[4][4];
#pragma unroll
        for (int mi = 0; mi < 4; mi++) {
            ldsm_x4(ahi[mi], aOffHi[mi] + so);
            ldsm_x4(alo[mi], aOffLo[mi] + so);
        }
#pragma unroll
        for (int np = 0; np < 4; np++) {
            uint32_t bh[4], bl[4];
            ldsm_x4t(bh, bOffHi[np] + so);
            ldsm_x4t(bl, bOffLo[np] + so);
#pragma unroll
            for (int mi = 0; mi < 4; mi++) {
                mma16816(acc[mi][2 * np],     ahi[mi], bh[0], bh[1]);
                mma16816(acc[mi][2 * np],     ahi[mi], bl[0], bl[1]);
                mma16816(acc[mi][2 * np],     alo[mi], bh[0], bh[1]);
                mma16816(acc[mi][2 * np + 1], ahi[mi], bh[2], bh[3]);
                mma16816(acc[mi][2 * np + 1], ahi[mi], bl[2], bl[3]);
                mma16816(acc[mi][2 * np + 1], alo[mi], bh[2], bh[3]);
            }
        }
        if (++sc >= STAGES) sc = 0;
    }

    // epilogue
    const int grp = lane >> 2;
    const int qd  = lane & 3;
#pragma unroll
    for (int mi = 0; mi < 4; mi++) {
#pragma unroll
        for (int ni = 0; ni < 8; ni++) {
            int col = n0 + wn * 64 + ni * 8 + qd * 2;
            float bx = bias[col], by = bias[col + 1];
            long row0 = m0 + wm * 64 + mi * 16 + grp;
            float v0 = acc[mi][ni][0] + bx, v1 = acc[mi][ni][1] + by;
            float v2 = acc[mi][ni][2] + bx, v3 = acc[mi][ni][3] + by;
            if (RELU) {
                v0 = fmaxf(v0, 0.f); v1 = fmaxf(v1, 0.f);
                v2 = fmaxf(v2, 0.f); v3 = fmaxf(v3, 0.f);
            }
            if (WF32) {
                *(float2*)&C[row0 * N + col] = make_float2(v0, v1);
                *(float2*)&C[(row0 + 8) * N + col] = make_float2(v2, v3);
            }
            if (WHILO) {
                uint32_t h0, l0, h1, l1;
                cvt2(v0, v1, h0, l0);
                cvt2(v2, v3, h1, l1);
                *(uint32_t*)&Chi[row0 * N + col] = h0;
                *(uint32_t*)&Clo[row0 * N + col] = l0;
                *(uint32_t*)&Chi[(row0 + 8) * N + col] = h1;
                *(uint32_t*)&Clo[(row0 + 8) * N + col] = l1;
            }
        }
    }
}

// ---------------------------------------------------------------------------
// Tensor-core causal flash attention with 2-stage cp.async K/V double buffer.
// Block = 128 threads (4 warps), 64 q-rows. Q resident in smem+regs.
// ---------------------------------------------------------------------------
#define KVS 72
#define QB (64 * KVS * 2)              // 9216 bytes per 64x64 bf16 buffer
#define ATTN_SMEM (10 * QB)            // Qh,Ql + 2 stages x (Kh,Kl,Vh,Vl)

__global__ void __launch_bounds__(128)
attn_tc_kernel(const bf16* __restrict__ Qhi, const bf16* __restrict__ Qlo,
               const bf16* __restrict__ Khi, const bf16* __restrict__ Klo,
               const bf16* __restrict__ Vhi, const bf16* __restrict__ Vlo,
               float* __restrict__ O) {
    extern __shared__ bf16 sbuf[];
    bf16* sQh = sbuf;
    bf16* sQl = sbuf + 64 * KVS;
    const uint32_t sbase = (uint32_t)__cvta_generic_to_shared(sbuf);

    const int tid  = threadIdx.x;
    const int lane = tid & 31;
    const int wq   = tid >> 5;
    const int grp  = lane >> 2;
    const int qd   = lane & 3;
    const int qt = gridDim.x - 1 - blockIdx.x;
    const int h  = blockIdx.y;
    const int b  = blockIdx.z;
    const int q0 = qt * 64;
    const long base = (long)b * S_ * DIM_ + h * DPH_;

    // K/V stage loader: 16 cp.async per thread per stage
    auto issue_kv = [&](int s, int k0) {
        const uint32_t st = sbase + 2 * QB + s * 4 * QB;
#pragma unroll
        for (int it = 0; it < 4; it++) {
            int id = tid + it * 128;
            int r = id >> 3, c = (id & 7) << 3;
            long g = base + (long)(k0 + r) * DIM_ + c;
            uint32_t d = st + (r * KVS + c) * 2;
            cp16(d,          &Khi[g]);
            cp16(d + QB,     &Klo[g]);
            cp16(d + 2 * QB, &Vhi[g]);
            cp16(d + 3 * QB, &Vlo[g]);
        }
    };

    // prologue: start kv tile 0 immediately
    issue_kv(0, 0);
    asm volatile("cp.async.commit_group;");

    // load Q tile (plain stores; independent of cp.async buffers)
    for (int i = tid; i < 64 * 8; i += 128) {
        int r = i >> 3, c = (i & 7) << 3;
        long g = base + (long)(q0 + r) * DIM_ + c;
        *(uint4*)&sQh[r * KVS + c] = *(const uint4*)&Qhi[g];
        *(uint4*)&sQl[r * KVS + c] = *(const uint4*)&Qlo[g];
    }
    __syncthreads();

    uint32_t qh[4][4], ql[4][4];
    {
        int arow = wq * 16 + (lane & 15);
        int acol = (lane >> 4) << 3;
#pragma unroll
        for (int kc = 0; kc < 4; kc++) {
            ldsm_x4(qh[kc], sbase + (arow * KVS + kc * 16 + acol) * 2);
            ldsm_x4(ql[kc], sbase + QB + (arow * KVS + kc * 16 + acol) * 2);
        }
    }

    float accO[8][4];
#pragma unroll
    for (int nd = 0; nd < 8; nd++)
#pragma unroll
        for (int r = 0; r < 4; r++) accO[nd][r] = 0.f;
    float m0 = -1e30f, m1 = -1e30f, l0 = 0.f, l1 = 0.f;
    const float sl2e = 1.4426950408889634f / 64.f;

    const int row0l = wq * 16 + grp;
    const int row1l = row0l + 8;

    const int kRow8 = lane & 7;
    const int kColSel = (lane >> 3) & 1;
    const int kNiSel  = (lane >> 4) & 1;
    const int vRow = lane & 15;
    const int vNdSel = (lane >> 4) & 1;

    for (int kt = 0; kt <= qt; kt++) {
        __syncthreads();   // all warps done with buf (kt+1)&1's previous use
        if (kt + 1 <= qt) issue_kv((kt + 1) & 1, (kt + 1) * 64);
        asm volatile("cp.async.commit_group;");
        asm volatile("cp.async.wait_group 1;");   // tile kt arrived (this thread)
        __syncthreads();                          // ... and all threads

        const uint32_t stS = sbase + 2 * QB + (kt & 1) * 4 * QB;

        float accS[8][4];
#pragma unroll
        for (int ni = 0; ni < 8; ni++)
#pragma unroll
            for (int r = 0; r < 4; r++) accS[ni][r] = 0.f;

#pragma unroll
        for (int kc = 0; kc < 4; kc++) {
#pragma unroll
            for (int np = 0; np < 4; np++) {
                uint32_t kh[4], kl[4];
                int off = (((2 * np + kNiSel) * 8 + kRow8) * KVS
                           + kc * 16 + kColSel * 8) * 2;
                ldsm_x4(kh, stS + off);
                ldsm_x4(kl, stS + QB + off);
                mma16816(accS[2 * np],     qh[kc], kh[0], kh[1]);
                mma16816(accS[2 * np],     qh[kc], kl[0], kl[1]);
                mma16816(accS[2 * np],     ql[kc], kh[0], kh[1]);
                mma16816(accS[2 * np + 1], qh[kc], kh[2], kh[3]);
                mma16816(accS[2 * np + 1], qh[kc], kl[2], kl[3]);
                mma16816(accS[2 * np + 1], ql[kc], kh[2], kh[3]);
            }
        }

        const bool diag = (kt == qt);
        float mt0 = -1e30f, mt1 = -1e30f;
#pragma unroll
        for (int ni = 0; ni < 8; ni++) {
            int colb = ni * 8 + qd * 2;
            float a0 = accS[ni][0] * sl2e, a1 = accS[ni][1] * sl2e;
            float a2 = accS[ni][2] * sl2e, a3 = accS[ni][3] * sl2e;
            if (diag) {
                if (colb     > row0l) a0 = -1e30f;
                if (colb + 1 > row0l) a1 = -1e30f;
                if (colb     > row1l) a2 = -1e30f;
                if (colb + 1 > row1l) a3 = -1e30f;
            }
            accS[ni][0] = a0; accS[ni][1] = a1;
            accS[ni][2] = a2; accS[ni][3] = a3;
            mt0 = fmaxf(mt0, fmaxf(a0, a1));
            mt1 = fmaxf(mt1, fmaxf(a2, a3));
        }
        mt0 = fmaxf(mt0, __shfl_xor_sync(0xffffffffu, mt0, 1));
        mt0 = fmaxf(mt0, __shfl_xor_sync(0xffffffffu, mt0, 2));
        mt1 = fmaxf(mt1, __shfl_xor_sync(0xffffffffu, mt1, 1));
        mt1 = fmaxf(mt1, __shfl_xor_sync(0xffffffffu, mt1, 2));

        float mn0 = fmaxf(m0, mt0), mn1 = fmaxf(m1, mt1);
        float c0 = exp2f(m0 - mn0), c1 = exp2f(m1 - mn1);
        m0 = mn0; m1 = mn1;

        float s0 = 0.f, s1 = 0.f;
#pragma unroll
        for (int ni = 0; ni < 8; ni++) {
            float p0 = exp2f(accS[ni][0] - mn0);
            float p1 = exp2f(accS[ni][1] - mn0);
            float p2 = exp2f(accS[ni][2] - mn1);
            float p3 = exp2f(accS[ni][3] - mn1);
            accS[ni][0] = p0; accS[ni][1] = p1;
            accS[ni][2] = p2; accS[ni][3] = p3;
            s0 += p0 + p1; s1 += p2 + p3;
        }
        s0 += __shfl_xor_sync(0xffffffffu, s0, 1);
        s0 += __shfl_xor_sync(0xffffffffu, s0, 2);
        s1 += __shfl_xor_sync(0xffffffffu, s1, 1);
        s1 += __shfl_xor_sync(0xffffffffu, s1, 2);
        l0 = l0 * c0 + s0;
        l1 = l1 * c1 + s1;

#pragma unroll
        for (int nd = 0; nd < 8; nd++) {
            accO[nd][0] *= c0; accO[nd][1] *= c0;
            accO[nd][2] *= c1; accO[nd][3] *= c1;
        }

#pragma unroll
        for (int kc2 = 0; kc2 < 4; kc2++) {
            uint32_t ph[4], pl[4];
            cvt2(accS[2 * kc2][0],     accS[2 * kc2][1],     ph[0], pl[0]);
            cvt2(accS[2 * kc2][2],     accS[2 * kc2][3],     ph[1], pl[1]);
            cvt2(accS[2 * kc2 + 1][0], accS[2 * kc2 + 1][1], ph[2], pl[2]);
            cvt2(accS[2 * kc2 + 1][2], accS[2 * kc2 + 1][3], ph[3], pl[3]);
#pragma unroll
            for (int np = 0; np < 4; np++) {
                uint32_t vh[4], vl[4];
                int off = ((kc2 * 16 + vRow) * KVS + (2 * np + vNdSel) * 8) * 2;
                ldsm_x4t(vh, stS + 2 * QB + off);
                ldsm_x4t(vl, stS + 3 * QB + off);
                mma16816(accO[2 * np],     ph, vh[0], vh[1]);
                mma16816(accO[2 * np],     pl, vh[0], vh[1]);
                mma16816(accO[2 * np],     ph, vl[0], vl[1]);
                mma16816(accO[2 * np + 1], ph, vh[2], vh[3]);
                mma16816(accO[2 * np + 1], pl, vh[2], vh[3]);
                mma16816(accO[2 * np + 1], ph, vl[2], vl[3]);
            }
        }
    }

    const float il0 = 1.f / l0, il1 = 1.f / l1;
    const long row0 = q0 + row0l;
#pragma unroll
    for (int nd = 0; nd < 8; nd++) {
        int d = nd * 8 + qd * 2;
        *(float2*)&O[base + row0 * DIM_ + d] =
            make_float2(accO[nd][0] * il0, accO[nd][1] * il0);
        *(float2*)&O[base + (row0 + 8) * DIM_ + d] =
            make_float2(accO[nd][2] * il1, accO[nd][3] * il1);
    }
}

// ---------------------------------------------------------------------------
// out = LayerNorm(A + R) * g + beta ; optionally also bf16 hi/lo of out
// ---------------------------------------------------------------------------
template <bool HILO>
__global__ void __launch_bounds__(256)
add_ln_kernel(const float* __restrict__ A, const float* __restrict__ R,
              const float* __restrict__ g, const float* __restrict__ beta,
              float* __restrict__ out, bf16* __restrict__ ohi,
              bf16* __restrict__ olo) {
    __shared__ float red[16];
    const int row = blockIdx.x;
    const int tid = threadIdx.x;
    const long off = (long)row * DIM_;

    float4 av = ((const float4*)(A + off))[tid];
    float4 rv = ((const float4*)(R + off))[tid];
    float v0 = av.x + rv.x, v1 = av.y + rv.y, v2 = av.z + rv.z, v3 = av.w + rv.w;
    float s  = v0 + v1 + v2 + v3;
    float sq = v0 * v0 + v1 * v1 + v2 * v2 + v3 * v3;
#pragma unroll
    for (int o = 16; o; o >>= 1) {
        s  += __shfl_xor_sync(0xffffffffu, s,  o);
        sq += __shfl_xor_sync(0xffffffffu, sq, o);
    }
    const int w = tid >> 5;
    if ((tid & 31) == 0) { red[w] = s; red[8 + w] = sq; }
    __syncthreads();
    s  = red[0] + red[1] + red[2] + red[3] + red[4] + red[5] + red[6] + red[7];
    sq = red[8] + red[9] + red[10] + red[11] + red[12] + red[13] + red[14] + red[15];

    const float mu  = s * (1.f / DIM_);
    const float var = sq * (1.f / DIM_) - mu * mu;
    const float rstd = rsqrtf(var + 1e-5f);

    float4 gv = ((const float4*)g)[tid];
    float4 bv = ((const float4*)beta)[tid];
    float4 ov;
    ov.x = (v0 - mu) * rstd * gv.x + bv.x;
    ov.y = (v1 - mu) * rstd * gv.y + bv.y;
    ov.z = (v2 - mu) * rstd * gv.z + bv.z;
    ov.w = (v3 - mu) * rstd * gv.w + bv.w;
    ((float4*)(out + off))[tid] = ov;
    if (HILO) {
        uint32_t h0, l0, h1, l1;
        cvt2(ov.x, ov.y, h0, l0); cvt2(ov.z, ov.w, h1, l1);
        ((uint2*)(ohi + off))[tid] = make_uint2(h0, h1);
        ((uint2*)(olo + off))[tid] = make_uint2(l0, l1);
    }
}

// ---------------------------------------------------------------------------
// Launch
// ---------------------------------------------------------------------------
static float* dsym(const void* sym) {
    void* p = nullptr;
    cudaGetSymbolAddress(&p, sym);
    return (float*)p;
}

extern "C" void kernel_launch(void* const* d_in, const int* in_sizes, int n_in,
                              void* d_out, int out_size) {
    const float* x    = (const float*)d_in[0];
    const float* Wq   = (const float*)d_in[1];
    const float* Wk   = (const float*)d_in[2];
    const float* Wv   = (const float*)d_in[3];
    const float* bq   = (const float*)d_in[4];
    const float* bk   = (const float*)d_in[5];
    const float* bv   = (const float*)d_in[6];
    const float* ln1g = (const float*)d_in[7];
    const float* ln1b = (const float*)d_in[8];
    const float* W1   = (const float*)d_in[9];
    const float* b1   = (const float*)d_in[10];
    const float* W2   = (const float*)d_in[11];
    const float* b2   = (const float*)d_in[12];
    const float* ln2g = (const float*)d_in[13];
    const float* ln2b = (const float*)d_in[14];
    float* out = (float*)d_out;

    float* attn = dsym(g_attn);
    float* h    = dsym(g_h);
    float* ffn  = dsym(g_ffn);
    bf16 *xhi = (bf16*)dsym(g_xhi), *xlo = (bf16*)dsym(g_xlo);
    bf16 *wqhi = (bf16*)dsym(g_wqhi), *wqlo = (bf16*)dsym(g_wqlo);
    bf16 *wkhi = (bf16*)dsym(g_wkhi), *wklo = (bf16*)dsym(g_wklo);
    bf16 *wvhi = (bf16*)dsym(g_wvhi), *wvlo = (bf16*)dsym(g_wvlo);
    bf16 *w1hi = (bf16*)dsym(g_w1hi), *w1lo = (bf16*)dsym(g_w1lo);
    bf16 *w2hi = (bf16*)dsym(g_w2hi), *w2lo = (bf16*)dsym(g_w2lo);
    bf16 *qhi = (bf16*)dsym(g_qhi), *qlo = (bf16*)dsym(g_qlo);
    bf16 *khi = (bf16*)dsym(g_khi), *klo = (bf16*)dsym(g_klo);
    bf16 *vhi = (bf16*)dsym(g_vhi), *vlo = (bf16*)dsym(g_vlo);
    bf16 *hhi = (bf16*)dsym(g_hhi), *hlo = (bf16*)dsym(g_hlo);
    bf16 *midhi = (bf16*)dsym(g_midhi), *midlo = (bf16*)dsym(g_midlo);

    cudaFuncSetAttribute(gemm_mma_kernel<false, false, true>,
                         cudaFuncAttributeMaxDynamicSharedMemorySize, GEMM_SMEM);
    cudaFuncSetAttribute(gemm_mma_kernel<true, false, true>,
                         cudaFuncAttributeMaxDynamicSharedMemorySize, GEMM_SMEM);
    cudaFuncSetAttribute(gemm_mma_kernel<false, true, false>,
                         cudaFuncAttributeMaxDynamicSharedMemorySize, GEMM_SMEM);
    cudaFuncSetAttribute(attn_tc_kernel,
                         cudaFuncAttributeMaxDynamicSharedMemorySize, ATTN_SMEM);

    auto split = [&](const float* src, bf16* hi, bf16* lo, long n) {
        int n4 = (int)(n / 4);
        split_kernel<<<(n4 + 255) / 256, 256>>>(src, hi, lo, n4);
    };

    // operand splits
    split(x,  xhi,  xlo,  (long)M_TOK * DIM_);
    split(Wq, wqhi, wqlo, (long)DIM_ * DIM_);
    split(Wk, wkhi, wklo, (long)DIM_ * DIM_);
    split(Wv, wvhi, wvlo, (long)DIM_ * DIM_);
    split(W1, w1hi, w1lo, (long)DIM_ * HID_);
    split(W2, w2hi, w2lo, (long)HID_ * DIM_);

    // QKV projections
    gemm_mma_kernel<false, false, true><<<dim3(8, 64), 128, GEMM_SMEM>>>(
        xhi, xlo, wqhi, wqlo, bq, nullptr, qhi, qlo, M_TOK, DIM_, DIM_);
    gemm_mma_kernel<false, false, true><<<dim3(8, 64), 128, GEMM_SMEM>>>(
        xhi, xlo, wkhi, wklo, bk, nullptr, khi, klo, M_TOK, DIM_, DIM_);
    gemm_mma_kernel<false, false, true><<<dim3(8, 64), 128, GEMM_SMEM>>>(
        xhi, xlo, wvhi, wvlo, bv, nullptr, vhi, vlo, M_TOK, DIM_, DIM_);

    // attention
    attn_tc_kernel<<<dim3(S_ / 64, NH_, B_), 128, ATTN_SMEM>>>(
        qhi, qlo, khi, klo, vhi, vlo, attn);

    // Add & Norm 1
    add_ln_kernel<true><<<M_TOK, 256>>>(attn, x, ln1g, ln1b, h, hhi, hlo);

    // FFN
    gemm_mma_kernel<true, false, true><<<dim3(32, 64), 128, GEMM_SMEM>>>(
        hhi, hlo, w1hi, w1lo, b1, nullptr, midhi, midlo, M_TOK, HID_, DIM_);
    gemm_mma_kernel<false, true, false><<<dim3(8, 64), 128, GEMM_SMEM>>>(
        midhi, midlo, w2hi, w2lo, b2, ffn, nullptr, nullptr, M_TOK, DIM_, HID_);

    // Add & Norm 2
    add_ln_kernel<false><<<M_TOK, 256>>>(ffn, h, ln2g, ln2b, out, nullptr, nullptr);
}

// round 17
// speedup vs baseline: 1.5310x; 1.5310x over previous
#include <cuda_runtime.h>
#include <cuda_bf16.h>
#include <cstdint>

// ---------------------------------------------------------------------------
// Transformer block: B=4, S=2048, DIM=1024, 16 heads, dph=64
// All matmuls on tensor cores via mma.sync split-bf16 (hi/lo).
// GEMM: CTA 128x128, 4 warps (64x64 warp tile), 3-stage cp.async ring.
// QKV fused into one launch (blockIdx selects weight).
// ---------------------------------------------------------------------------

#define B_ 4
#define S_ 2048
#define DIM_ 1024
#define NH_ 16
#define DPH_ 64
#define M_TOK (B_ * S_)        // 8192
#define HID_ (4 * DIM_)        // 4096

typedef __nv_bfloat16 bf16;

// fp32 scratch
__device__ float g_attn[M_TOK * DIM_];
__device__ float g_h[M_TOK * DIM_];
__device__ float g_ffn[M_TOK * DIM_];
// bf16 hi/lo operand scratch (weights in natural [K][N] layout)
__device__ bf16 g_xhi[M_TOK * DIM_],  g_xlo[M_TOK * DIM_];
__device__ bf16 g_wqhi[DIM_ * DIM_],  g_wqlo[DIM_ * DIM_];
__device__ bf16 g_wkhi[DIM_ * DIM_],  g_wklo[DIM_ * DIM_];
__device__ bf16 g_wvhi[DIM_ * DIM_],  g_wvlo[DIM_ * DIM_];
__device__ bf16 g_w1hi[DIM_ * HID_],  g_w1lo[DIM_ * HID_];
__device__ bf16 g_w2hi[HID_ * DIM_],  g_w2lo[HID_ * DIM_];
__device__ bf16 g_qhi[M_TOK * DIM_],  g_qlo[M_TOK * DIM_];
__device__ bf16 g_khi[M_TOK * DIM_],  g_klo[M_TOK * DIM_];
__device__ bf16 g_vhi[M_TOK * DIM_],  g_vlo[M_TOK * DIM_];
__device__ bf16 g_hhi[M_TOK * DIM_],  g_hlo[M_TOK * DIM_];
__device__ bf16 g_midhi[M_TOK * HID_], g_midlo[M_TOK * HID_];

// ---------------------------------------------------------------------------
// helpers
// ---------------------------------------------------------------------------
__device__ __forceinline__ void ldsm_x4(uint32_t (&r)[4], uint32_t addr) {
    asm volatile("ldmatrix.sync.aligned.m8n8.x4.shared.b16 {%0,%1,%2,%3}, [%4];"
                 : "=r"(r[0]), "=r"(r[1]), "=r"(r[2]), "=r"(r[3]) : "r"(addr));
}
__device__ __forceinline__ void ldsm_x4t(uint32_t (&r)[4], uint32_t addr) {
    asm volatile("ldmatrix.sync.aligned.m8n8.x4.trans.shared.b16 {%0,%1,%2,%3}, [%4];"
                 : "=r"(r[0]), "=r"(r[1]), "=r"(r[2]), "=r"(r[3]) : "r"(addr));
}
__device__ __forceinline__ void mma16816(float (&d)[4], const uint32_t (&a)[4],
                                         uint32_t b0, uint32_t b1) {
    asm volatile(
        "mma.sync.aligned.m16n8k16.row.col.f32.bf16.bf16.f32 "
        "{%0,%1,%2,%3}, {%4,%5,%6,%7}, {%8,%9}, {%0,%1,%2,%3};"
        : "+f"(d[0]), "+f"(d[1]), "+f"(d[2]), "+f"(d[3])
        : "r"(a[0]), "r"(a[1]), "r"(a[2]), "r"(a[3]), "r"(b0), "r"(b1));
}
__device__ __forceinline__ void cvt2(float x, float y, uint32_t& hi, uint32_t& lo) {
    bf16 hx = __float2bfloat16_rn(x);
    bf16 hy = __float2bfloat16_rn(y);
    bf16 lx = __float2bfloat16_rn(x - __bfloat162float(hx));
    bf16 ly = __float2bfloat16_rn(y - __bfloat162float(hy));
    hi = (uint32_t)__bfloat16_as_ushort(hx) | ((uint32_t)__bfloat16_as_ushort(hy) << 16);
    lo = (uint32_t)__bfloat16_as_ushort(lx) | ((uint32_t)__bfloat16_as_ushort(ly) << 16);
}
__device__ __forceinline__ void cp16(uint32_t dst, const void* src) {
    asm volatile("cp.async.cg.shared.global [%0], [%1], 16;" :: "r"(dst), "l"(src));
}

// ---------------------------------------------------------------------------
// elementwise split: fp32 -> bf16 hi/lo
// ---------------------------------------------------------------------------
__global__ void __launch_bounds__(256)
split_kernel(const float* __restrict__ in, bf16* __restrict__ hi,
             bf16* __restrict__ lo, int n4) {
    int i = blockIdx.x * blockDim.x + threadIdx.x;
    if (i < n4) {
        float4 v = ((const float4*)in)[i];
        uint32_t h0, l0, h1, l1;
        cvt2(v.x, v.y, h0, l0); cvt2(v.z, v.w, h1, l1);
        ((uint2*)hi)[i] = make_uint2(h0, h1);
        ((uint2*)lo)[i] = make_uint2(l0, l1);
    }
}

// ---------------------------------------------------------------------------
// GEMM core (shared by generic + fused-QKV kernels).
// CTA 128x128, 128 threads (4 warps, 2m x 2n, warp 64x64),
// k-step 16, 3-stage cp.async ring. Split-bf16 (3 mma per logical mma).
// ---------------------------------------------------------------------------
#define AS 24          // A smem row stride (bf16) = 48B
#define BS 136         // B smem row stride (bf16) = 272B
#define A_BYTES (128 * AS * 2)          // 6144
#define B_BYTES (16 * BS * 2)           // 4352
#define SSTRIDE (2 * A_BYTES + 2 * B_BYTES)   // 20992 per stage
#define STAGES 3
#define GEMM_SMEM (STAGES * SSTRIDE)    // 62976

template <bool RELU, bool WF32, bool WHILO>
__device__ __forceinline__ void gemm_body(
    const bf16* __restrict__ Ahi, const bf16* __restrict__ Alo,
    const bf16* __restrict__ Bhi, const bf16* __restrict__ Blo,
    const float* __restrict__ bias, float* __restrict__ C,
    bf16* __restrict__ Chi, bf16* __restrict__ Clo,
    int N, int K, int m0, int n0, char* smem) {
    const uint32_t sbase = (uint32_t)__cvta_generic_to_shared(smem);

    const int tid  = threadIdx.x;
    const int lane = tid & 31;
    const int wid  = tid >> 5;
    const int wm   = wid & 1;       // 64-row half
    const int wn   = wid >> 1;      // 64-col half

    // loaders (128 threads)
    const bf16* Aph = Ahi + (long)(m0 + tid) * K;
    const bf16* Apl = Alo + (long)(m0 + tid) * K;
    const uint32_t aHd = sbase + (tid * AS) * 2;
    const int bk = tid >> 3;
    const int bc = (tid & 7) << 4;
    const bf16* Bph = Bhi + (long)bk * N + n0 + bc;
    const bf16* Bpl = Blo + (long)bk * N + n0 + bc;
    const uint32_t bHd = sbase + 2 * A_BYTES + (bk * BS + bc) * 2;

    // ldmatrix offsets (within a stage)
    const int arow = lane & 15;
    const int acolg = (lane >> 4) << 3;
    uint32_t aOffHi[4], aOffLo[4];
#pragma unroll
    for (int mi = 0; mi < 4; mi++) {
        int off = ((wm * 64 + mi * 16 + arow) * AS + acolg) * 2;
        aOffHi[mi] = sbase + off;
        aOffLo[mi] = sbase + A_BYTES + off;
    }
    const int bRow = lane & 15;
    const int bNdSel = (lane >> 4) & 1;
    uint32_t bOffHi[4], bOffLo[4];
#pragma unroll
    for (int np = 0; np < 4; np++) {
        int off = (bRow * BS + wn * 64 + (2 * np + bNdSel) * 8) * 2;
        bOffHi[np] = sbase + 2 * A_BYTES + off;
        bOffLo[np] = sbase + 2 * A_BYTES + B_BYTES + off;
    }

    float acc[4][8][4];
#pragma unroll
    for (int mi = 0; mi < 4; mi++)
#pragma unroll
        for (int ni = 0; ni < 8; ni++)
#pragma unroll
            for (int r = 0; r < 4; r++) acc[mi][ni][r] = 0.f;

    const int nk = K >> 4;

    auto issue_stage = [&](int s, int k0) {
        const uint32_t so = s * SSTRIDE;
        cp16(aHd + so,      Aph + k0);
        cp16(aHd + so + 16, Aph + k0 + 8);
        cp16(aHd + so + A_BYTES,      Apl + k0);
        cp16(aHd + so + A_BYTES + 16, Apl + k0 + 8);
        cp16(bHd + so,      Bph + (long)k0 * N);
        cp16(bHd + so + 16, Bph + (long)k0 * N + 8);
        cp16(bHd + so + B_BYTES,      Bpl + (long)k0 * N);
        cp16(bHd + so + B_BYTES + 16, Bpl + (long)k0 * N + 8);
    };

    // prologue: stages 0,1
    issue_stage(0, 0);
    asm volatile("cp.async.commit_group;");
    if (nk > 1) issue_stage(1, 16);
    asm volatile("cp.async.commit_group;");

    int sc = 0;   // stage being computed
    for (int kt = 0; kt < nk; kt++) {
        asm volatile("cp.async.wait_group %0;" :: "n"(1));
        __syncthreads();

        // issue stage kt+2
        if (kt + 2 < nk) {
            int sw = sc + 2; if (sw >= STAGES) sw -= STAGES;
            issue_stage(sw, (kt + 2) << 4);
        }
        asm volatile("cp.async.commit_group;");

        // compute stage sc
        const uint32_t so = sc * SSTRIDE;
        uint32_t ahi[4][4], alo[4][4];
#pragma unroll
        for (int mi = 0; mi < 4; mi++) {
            ldsm_x4(ahi[mi], aOffHi[mi] + so);
            ldsm_x4(alo[mi], aOffLo[mi] + so);
        }
#pragma unroll
        for (int np = 0; np < 4; np++) {
            uint32_t bh[4], bl[4];
            ldsm_x4t(bh, bOffHi[np] + so);
            ldsm_x4t(bl, bOffLo[np] + so);
#pragma unroll
            for (int mi = 0; mi < 4; mi++) {
                mma16816(acc[mi][2 * np],     ahi[mi], bh[0], bh[1]);
                mma16816(acc[mi][2 * np],     ahi[mi], bl[0], bl[1]);
                mma16816(acc[mi][2 * np],     alo[mi], bh[0], bh[1]);
                mma16816(acc[mi][2 * np + 1], ahi[mi], bh[2], bh[3]);
                mma16816(acc[mi][2 * np + 1], ahi[mi], bl[2], bl[3]);
                mma16816(acc[mi][2 * np + 1], alo[mi], bh[2], bh[3]);
            }
        }
        if (++sc >= STAGES) sc = 0;
    }

    // epilogue
    const int grp = lane >> 2;
    const int qd  = lane & 3;
#pragma unroll
    for (int mi = 0; mi < 4; mi++) {
#pragma unroll
        for (int ni = 0; ni < 8; ni++) {
            int col = n0 + wn * 64 + ni * 8 + qd * 2;
            float bx = bias[col], by = bias[col + 1];
            long row0 = m0 + wm * 64 + mi * 16 + grp;
            float v0 = acc[mi][ni][0] + bx, v1 = acc[mi][ni][1] + by;
            float v2 = acc[mi][ni][2] + bx, v3 = acc[mi][ni][3] + by;
            if (RELU) {
                v0 = fmaxf(v0, 0.f); v1 = fmaxf(v1, 0.f);
                v2 = fmaxf(v2, 0.f); v3 = fmaxf(v3, 0.f);
            }
            if (WF32) {
                *(float2*)&C[row0 * N + col] = make_float2(v0, v1);
                *(float2*)&C[(row0 + 8) * N + col] = make_float2(v2, v3);
            }
            if (WHILO) {
                uint32_t h0, l0, h1, l1;
                cvt2(v0, v1, h0, l0);
                cvt2(v2, v3, h1, l1);
                *(uint32_t*)&Chi[row0 * N + col] = h0;
                *(uint32_t*)&Clo[row0 * N + col] = l0;
                *(uint32_t*)&Chi[(row0 + 8) * N + col] = h1;
                *(uint32_t*)&Clo[(row0 + 8) * N + col] = l1;
            }
        }
    }
}

template <bool RELU, bool WF32, bool WHILO>
__global__ void __launch_bounds__(128, 2)
gemm_mma_kernel(const bf16* __restrict__ Ahi, const bf16* __restrict__ Alo,
                const bf16* __restrict__ Bhi, const bf16* __restrict__ Blo,
                const float* __restrict__ bias, float* __restrict__ C,
                bf16* __restrict__ Chi, bf16* __restrict__ Clo,
                int M, int N, int K) {
    extern __shared__ char smem[];
    gemm_body<RELU, WF32, WHILO>(Ahi, Alo, Bhi, Blo, bias, C, Chi, Clo,
                                 N, K, blockIdx.y << 7, blockIdx.x << 7, smem);
}

// Fused QKV: grid.x = 24 (8 n-tiles x 3 weights); blockIdx.x>>3 selects weight.
__global__ void __launch_bounds__(128, 2)
qkv_mma_kernel(const bf16* __restrict__ Ahi, const bf16* __restrict__ Alo,
               const bf16* __restrict__ Wqh, const bf16* __restrict__ Wql,
               const bf16* __restrict__ Wkh, const bf16* __restrict__ Wkl,
               const bf16* __restrict__ Wvh, const bf16* __restrict__ Wvl,
               const float* __restrict__ bq, const float* __restrict__ bk,
               const float* __restrict__ bv,
               bf16* __restrict__ Qh, bf16* __restrict__ Ql,
               bf16* __restrict__ Kh, bf16* __restrict__ Kl,
               bf16* __restrict__ Vh, bf16* __restrict__ Vl) {
    extern __shared__ char smem[];
    const int wsel = blockIdx.x >> 3;
    const int n0 = (blockIdx.x & 7) << 7;
    const bf16 *Bh, *Bl; const float* bias; bf16 *Ch, *Cl;
    if (wsel == 0)      { Bh = Wqh; Bl = Wql; bias = bq; Ch = Qh; Cl = Ql; }
    else if (wsel == 1) { Bh = Wkh; Bl = Wkl; bias = bk; Ch = Kh; Cl = Kl; }
    else                { Bh = Wvh; Bl = Wvl; bias = bv; Ch = Vh; Cl = Vl; }
    gemm_body<false, false, true>(Ahi, Alo, Bh, Bl, bias, nullptr, Ch, Cl,
                                  DIM_, DIM_, blockIdx.y << 7, n0, smem);
}

// ---------------------------------------------------------------------------
// Tensor-core causal flash attention (mma.sync split-bf16, proven R14 form).
// ---------------------------------------------------------------------------
#define KVS 72
#define ATTN_SMEM (6 * 64 * KVS * 2)

__global__ void __launch_bounds__(128)
attn_tc_kernel(const bf16* __restrict__ Qhi, const bf16* __restrict__ Qlo,
               const bf16* __restrict__ Khi, const bf16* __restrict__ Klo,
               const bf16* __restrict__ Vhi, const bf16* __restrict__ Vlo,
               float* __restrict__ O) {
    extern __shared__ bf16 sbuf[];
    bf16* sQh = sbuf;
    bf16* sQl = sQh + 64 * KVS;
    bf16* sKh = sQl + 64 * KVS;
    bf16* sKl = sKh + 64 * KVS;
    bf16* sVh = sKl + 64 * KVS;
    bf16* sVl = sVh + 64 * KVS;

    const int tid  = threadIdx.x;
    const int lane = tid & 31;
    const int wq   = tid >> 5;
    const int grp  = lane >> 2;
    const int qd   = lane & 3;
    const int qt = gridDim.x - 1 - blockIdx.x;
    const int h  = blockIdx.y;
    const int b  = blockIdx.z;
    const int q0 = qt * 64;
    const long base = (long)b * S_ * DIM_ + h * DPH_;

    const uint32_t sQhB = (uint32_t)__cvta_generic_to_shared(sQh);
    const uint32_t sQlB = (uint32_t)__cvta_generic_to_shared(sQl);
    const uint32_t sKhB = (uint32_t)__cvta_generic_to_shared(sKh);
    const uint32_t sKlB = (uint32_t)__cvta_generic_to_shared(sKl);
    const uint32_t sVhB = (uint32_t)__cvta_generic_to_shared(sVh);
    const uint32_t sVlB = (uint32_t)__cvta_generic_to_shared(sVl);

    for (int i = tid; i < 64 * 8; i += 128) {
        int r = i >> 3, c = (i & 7) << 3;
        long g = base + (long)(q0 + r) * DIM_ + c;
        *(uint4*)&sQh[r * KVS + c] = *(const uint4*)&Qhi[g];
        *(uint4*)&sQl[r * KVS + c] = *(const uint4*)&Qlo[g];
    }
    __syncthreads();

    uint32_t qh[4][4], ql[4][4];
    {
        int arow = wq * 16 + (lane & 15);
        int acol = (lane >> 4) << 3;
#pragma unroll
        for (int kc = 0; kc < 4; kc++) {
            ldsm_x4(qh[kc], sQhB + (arow * KVS + kc * 16 + acol) * 2);
            ldsm_x4(ql[kc], sQlB + (arow * KVS + kc * 16 + acol) * 2);
        }
    }

    float accO[8][4];
#pragma unroll
    for (int nd = 0; nd < 8; nd++)
#pragma unroll
        for (int r = 0; r < 4; r++) accO[nd][r] = 0.f;
    float m0 = -1e30f, m1 = -1e30f, l0 = 0.f, l1 = 0.f;
    const float sl2e = 1.4426950408889634f / 64.f;

    const int row0l = wq * 16 + grp;
    const int row1l = row0l + 8;

    const int kRow8 = lane & 7;
    const int kColSel = (lane >> 3) & 1;
    const int kNiSel  = (lane >> 4) & 1;
    const int vRow = lane & 15;
    const int vNdSel = (lane >> 4) & 1;

    for (int kt = 0; kt <= qt; kt++) {
        const int k0 = kt * 64;
        __syncthreads();
        for (int i = tid; i < 64 * 8; i += 128) {
            int r = i >> 3, c = (i & 7) << 3;
            long g = base + (long)(k0 + r) * DIM_ + c;
            *(uint4*)&sKh[r * KVS + c] = *(const uint4*)&Khi[g];
            *(uint4*)&sKl[r * KVS + c] = *(const uint4*)&Klo[g];
            *(uint4*)&sVh[r * KVS + c] = *(const uint4*)&Vhi[g];
            *(uint4*)&sVl[r * KVS + c] = *(const uint4*)&Vlo[g];
        }
        __syncthreads();

        float accS[8][4];
#pragma unroll
        for (int ni = 0; ni < 8; ni++)
#pragma unroll
            for (int r = 0; r < 4; r++) accS[ni][r] = 0.f;

#pragma unroll
        for (int kc = 0; kc < 4; kc++) {
#pragma unroll
            for (int np = 0; np < 4; np++) {
                uint32_t kh[4], kl[4];
                int off = (((2 * np + kNiSel) * 8 + kRow8) * KVS
                           + kc * 16 + kColSel * 8) * 2;
                ldsm_x4(kh, sKhB + off);
                ldsm_x4(kl, sKlB + off);
                mma16816(accS[2 * np],     qh[kc], kh[0], kh[1]);
                mma16816(accS[2 * np],     qh[kc], kl[0], kl[1]);
                mma16816(accS[2 * np],     ql[kc], kh[0], kh[1]);
                mma16816(accS[2 * np + 1], qh[kc], kh[2], kh[3]);
                mma16816(accS[2 * np + 1], qh[kc], kl[2], kl[3]);
                mma16816(accS[2 * np + 1], ql[kc], kh[2], kh[3]);
            }
        }

        const bool diag = (kt == qt);
        float mt0 = -1e30f, mt1 = -1e30f;
#pragma unroll
        for (int ni = 0; ni < 8; ni++) {
            int colb = ni * 8 + qd * 2;
            float a0 = accS[ni][0] * sl2e, a1 = accS[ni][1] * sl2e;
            float a2 = accS[ni][2] * sl2e, a3 = accS[ni][3] * sl2e;
            if (diag) {
                if (colb     > row0l) a0 = -1e30f;
                if (colb + 1 > row0l) a1 = -1e30f;
                if (colb     > row1l) a2 = -1e30f;
                if (colb + 1 > row1l) a3 = -1e30f;
            }
            accS[ni][0] = a0; accS[ni][1] = a1;
            accS[ni][2] = a2; accS[ni][3] = a3;
            mt0 = fmaxf(mt0, fmaxf(a0, a1));
            mt1 = fmaxf(mt1, fmaxf(a2, a3));
        }
        mt0 = fmaxf(mt0, __shfl_xor_sync(0xffffffffu, mt0, 1));
        mt0 = fmaxf(mt0, __shfl_xor_sync(0xffffffffu, mt0, 2));
        mt1 = fmaxf(mt1, __shfl_xor_sync(0xffffffffu, mt1, 1));
        mt1 = fmaxf(mt1, __shfl_xor_sync(0xffffffffu, mt1, 2));

        float mn0 = fmaxf(m0, mt0), mn1 = fmaxf(m1, mt1);
        float c0 = exp2f(m0 - mn0), c1 = exp2f(m1 - mn1);
        m0 = mn0; m1 = mn1;

        float s0 = 0.f, s1 = 0.f;
#pragma unroll
        for (int ni = 0; ni < 8; ni++) {
            float p0 = exp2f(accS[ni][0] - mn0);
            float p1 = exp2f(accS[ni][1] - mn0);
            float p2 = exp2f(accS[ni][2] - mn1);
            float p3 = exp2f(accS[ni][3] - mn1);
            accS[ni][0] = p0; accS[ni][1] = p1;
            accS[ni][2] = p2; accS[ni][3] = p3;
            s0 += p0 + p1; s1 += p2 + p3;
        }
        s0 += __shfl_xor_sync(0xffffffffu, s0, 1);
        s0 += __shfl_xor_sync(0xffffffffu, s0, 2);
        s1 += __shfl_xor_sync(0xffffffffu, s1, 1);
        s1 += __shfl_xor_sync(0xffffffffu, s1, 2);
        l0 = l0 * c0 + s0;
        l1 = l1 * c1 + s1;

#pragma unroll
        for (int nd = 0; nd < 8; nd++) {
            accO[nd][0] *= c0; accO[nd][1] *= c0;
            accO[nd][2] *= c1; accO[nd][3] *= c1;
        }

#pragma unroll
        for (int kc2 = 0; kc2 < 4; kc2++) {
            uint32_t ph[4], pl[4];
            cvt2(accS[2 * kc2][0],     accS[2 * kc2][1],     ph[0], pl[0]);
            cvt2(accS[2 * kc2][2],     accS[2 * kc2][3],     ph[1], pl[1]);
            cvt2(accS[2 * kc2 + 1][0], accS[2 * kc2 + 1][1], ph[2], pl[2]);
            cvt2(accS[2 * kc2 + 1][2], accS[2 * kc2 + 1][3], ph[3], pl[3]);
#pragma unroll
            for (int np = 0; np < 4; np++) {
                uint32_t vh[4], vl[4];
                int off = ((kc2 * 16 + vRow) * KVS + (2 * np + vNdSel) * 8) * 2;
                ldsm_x4t(vh, sVhB + off);
                ldsm_x4t(vl, sVlB + off);
                mma16816(accO[2 * np],     ph, vh[0], vh[1]);
                mma16816(accO[2 * np],     pl, vh[0], vh[1]);
                mma16816(accO[2 * np],     ph, vl[0], vl[1]);
                mma16816(accO[2 * np + 1], ph, vh[2], vh[3]);
                mma16816(accO[2 * np + 1], pl, vh[2], vh[3]);
                mma16816(accO[2 * np + 1], ph, vl[2], vl[3]);
            }
        }
    }

    const float il0 = 1.f / l0, il1 = 1.f / l1;
    const long row0 = q0 + row0l;
#pragma unroll
    for (int nd = 0; nd < 8; nd++) {
        int d = nd * 8 + qd * 2;
        *(float2*)&O[base + row0 * DIM_ + d] =
            make_float2(accO[nd][0] * il0, accO[nd][1] * il0);
        *(float2*)&O[base + (row0 + 8) * DIM_ + d] =
            make_float2(accO[nd][2] * il1, accO[nd][3] * il1);
    }
}

// ---------------------------------------------------------------------------
// out = LayerNorm(A + R) * g + beta ; optionally also bf16 hi/lo of out
// ---------------------------------------------------------------------------
template <bool HILO>
__global__ void __launch_bounds__(256)
add_ln_kernel(const float* __restrict__ A, const float* __restrict__ R,
              const float* __restrict__ g, const float* __restrict__ beta,
              float* __restrict__ out, bf16* __restrict__ ohi,
              bf16* __restrict__ olo) {
    __shared__ float red[16];
    const int row = blockIdx.x;
    const int tid = threadIdx.x;
    const long off = (long)row * DIM_;

    float4 av = ((const float4*)(A + off))[tid];
    float4 rv = ((const float4*)(R + off))[tid];
    float v0 = av.x + rv.x, v1 = av.y + rv.y, v2 = av.z + rv.z, v3 = av.w + rv.w;
    float s  = v0 + v1 + v2 + v3;
    float sq = v0 * v0 + v1 * v1 + v2 * v2 + v3 * v3;
#pragma unroll
    for (int o = 16; o; o >>= 1) {
        s  += __shfl_xor_sync(0xffffffffu, s,  o);
        sq += __shfl_xor_sync(0xffffffffu, sq, o);
    }
    const int w = tid >> 5;
    if ((tid & 31) == 0) { red[w] = s; red[8 + w] = sq; }
    __syncthreads();
    s  = red[0] + red[1] + red[2] + red[3] + red[4] + red[5] + red[6] + red[7];
    sq = red[8] + red[9] + red[10] + red[11] + red[12] + red[13] + red[14] + red[15];

    const float mu  = s * (1.f / DIM_);
    const float var = sq * (1.f / DIM_) - mu * mu;
    const float rstd = rsqrtf(var + 1e-5f);

    float4 gv = ((const float4*)g)[tid];
    float4 bv = ((const float4*)beta)[tid];
    float4 ov;
    ov.x = (v0 - mu) * rstd * gv.x + bv.x;
    ov.y = (v1 - mu) * rstd * gv.y + bv.y;
    ov.z = (v2 - mu) * rstd * gv.z + bv.z;
    ov.w = (v3 - mu) * rstd * gv.w + bv.w;
    ((float4*)(out + off))[tid] = ov;
    if (HILO) {
        uint32_t h0, l0, h1, l1;
        cvt2(ov.x, ov.y, h0, l0); cvt2(ov.z, ov.w, h1, l1);
        ((uint2*)(ohi + off))[tid] = make_uint2(h0, h1);
        ((uint2*)(olo + off))[tid] = make_uint2(l0, l1);
    }
}

// ---------------------------------------------------------------------------
// Launch
// ---------------------------------------------------------------------------
static float* dsym(const void* sym) {
    void* p = nullptr;
    cudaGetSymbolAddress(&p, sym);
    return (float*)p;
}

extern "C" void kernel_launch(void* const* d_in, const int* in_sizes, int n_in,
                              void* d_out, int out_size) {
    const float* x    = (const float*)d_in[0];
    const float* Wq   = (const float*)d_in[1];
    const float* Wk   = (const float*)d_in[2];
    const float* Wv   = (const float*)d_in[3];
    const float* bq   = (const float*)d_in[4];
    const float* bk   = (const float*)d_in[5];
    const float* bv   = (const float*)d_in[6];
    const float* ln1g = (const float*)d_in[7];
    const float* ln1b = (const float*)d_in[8];
    const float* W1   = (const float*)d_in[9];
    const float* b1   = (const float*)d_in[10];
    const float* W2   = (const float*)d_in[11];
    const float* b2   = (const float*)d_in[12];
    const float* ln2g = (const float*)d_in[13];
    const float* ln2b = (const float*)d_in[14];
    float* out = (float*)d_out;

    float* attn = dsym(g_attn);
    float* h    = dsym(g_h);
    float* ffn  = dsym(g_ffn);
    bf16 *xhi = (bf16*)dsym(g_xhi), *xlo = (bf16*)dsym(g_xlo);
    bf16 *wqhi = (bf16*)dsym(g_wqhi), *wqlo = (bf16*)dsym(g_wqlo);
    bf16 *wkhi = (bf16*)dsym(g_wkhi), *wklo = (bf16*)dsym(g_wklo);
    bf16 *wvhi = (bf16*)dsym(g_wvhi), *wvlo = (bf16*)dsym(g_wvlo);
    bf16 *w1hi = (bf16*)dsym(g_w1hi), *w1lo = (bf16*)dsym(g_w1lo);
    bf16 *w2hi = (bf16*)dsym(g_w2hi), *w2lo = (bf16*)dsym(g_w2lo);
    bf16 *qhi = (bf16*)dsym(g_qhi), *qlo = (bf16*)dsym(g_qlo);
    bf16 *khi = (bf16*)dsym(g_khi), *klo = (bf16*)dsym(g_klo);
    bf16 *vhi = (bf16*)dsym(g_vhi), *vlo = (bf16*)dsym(g_vlo);
    bf16 *hhi = (bf16*)dsym(g_hhi), *hlo = (bf16*)dsym(g_hlo);
    bf16 *midhi = (bf16*)dsym(g_midhi), *midlo = (bf16*)dsym(g_midlo);

    cudaFuncSetAttribute(qkv_mma_kernel,
                         cudaFuncAttributeMaxDynamicSharedMemorySize, GEMM_SMEM);
    cudaFuncSetAttribute(gemm_mma_kernel<true, false, true>,
                         cudaFuncAttributeMaxDynamicSharedMemorySize, GEMM_SMEM);
    cudaFuncSetAttribute(gemm_mma_kernel<false, true, false>,
                         cudaFuncAttributeMaxDynamicSharedMemorySize, GEMM_SMEM);
    cudaFuncSetAttribute(attn_tc_kernel,
                         cudaFuncAttributeMaxDynamicSharedMemorySize, ATTN_SMEM);

    auto split = [&](const float* src, bf16* hi, bf16* lo, long n) {
        int n4 = (int)(n / 4);
        split_kernel<<<(n4 + 255) / 256, 256>>>(src, hi, lo, n4);
    };

    // operand splits
    split(x,  xhi,  xlo,  (long)M_TOK * DIM_);
    split(Wq, wqhi, wqlo, (long)DIM_ * DIM_);
    split(Wk, wkhi, wklo, (long)DIM_ * DIM_);
    split(Wv, wvhi, wvlo, (long)DIM_ * DIM_);
    split(W1, w1hi, w1lo, (long)DIM_ * HID_);
    split(W2, w2hi, w2lo, (long)HID_ * DIM_);

    // QKV projections: ONE fused launch (24 n-tiles x 64 m-tiles)
    qkv_mma_kernel<<<dim3(24, 64), 128, GEMM_SMEM>>>(
        xhi, xlo, wqhi, wqlo, wkhi, wklo, wvhi, wvlo,
        bq, bk, bv, qhi, qlo, khi, klo, vhi, vlo);

    // attention
    attn_tc_kernel<<<dim3(S_ / 64, NH_, B_), 128, ATTN_SMEM>>>(
        qhi, qlo, khi, klo, vhi, vlo, attn);

    // Add & Norm 1
    add_ln_kernel<true><<<M_TOK, 256>>>(attn, x, ln1g, ln1b, h, hhi, hlo);

    // FFN
    gemm_mma_kernel<true, false, true><<<dim3(32, 64), 128, GEMM_SMEM>>>(
        hhi, hlo, w1hi, w1lo, b1, nullptr, midhi, midlo, M_TOK, HID_, DIM_);
    gemm_mma_kernel<false, true, false><<<dim3(8, 64), 128, GEMM_SMEM>>>(
        midhi, midlo, w2hi, w2lo, b2, ffn, nullptr, nullptr, M_TOK, DIM_, HID_);

    // Add & Norm 2
    add_ln_kernel<false><<<M_TOK, 256>>>(ffn, h, ln2g, ln2b, out, nullptr, nullptr);
}